// round 1
// baseline (speedup 1.0000x reference)
#include <cuda_runtime.h>
#include <math.h>

// Scratch for precomputed GT box data: per box 12 floats:
// [0..7] 4 corners (x,y) CCW, [8] area, [9] cx, [10] cy, [11] enclosing radius
#define MAX_M 8192
__device__ float g_gt[MAX_M * 12];

__device__ __forceinline__ void box_corners(float x, float y, float dx, float dy,
                                            float yaw, float* cx, float* cy) {
    float hx = 0.5f * dx, hy = 0.5f * dy;
    float s, c;
    sincosf(yaw, &s, &c);
    // CCW: (hx,hy), (-hx,hy), (-hx,-hy), (hx,-hy) in local frame
    cx[0] = x + c * hx - s * hy;  cy[0] = y + s * hx + c * hy;
    cx[1] = x - c * hx - s * hy;  cy[1] = y - s * hx + c * hy;
    cx[2] = x - c * hx + s * hy;  cy[2] = y - s * hx - c * hy;
    cx[3] = x + c * hx + s * hy;  cy[3] = y + s * hx - c * hy;
}

// Prep: zero the output accumulator and precompute GT corners/area/circle.
__global__ void prep_kernel(const float* __restrict__ box_gt, int M,
                            float* __restrict__ out, int out_size) {
    int j = blockIdx.x * blockDim.x + threadIdx.x;
    if (j < out_size) out[j] = 0.0f;
    if (j < M) {
        const float* b = box_gt + j * 7;
        float x = b[0], y = b[1], dx = b[3], dy = b[4], yaw = b[6];
        float cx[4], cy[4];
        box_corners(x, y, dx, dy, yaw, cx, cy);
        float* g = g_gt + j * 12;
        #pragma unroll
        for (int k = 0; k < 4; k++) { g[2 * k] = cx[k]; g[2 * k + 1] = cy[k]; }
        g[8] = dx * dy;
        g[9] = x;
        g[10] = y;
        g[11] = 0.5f * sqrtf(dx * dx + dy * dy);
    }
}

// Main: one block per pred box. Stage all GT data in shared, each thread
// handles M/blockDim gt boxes, block-max-reduce, atomicAdd the loss term.
__global__ void iou_loss_kernel(const float* __restrict__ iou_pred,
                                const float* __restrict__ box_pred,
                                const void* __restrict__ ntp_raw,
                                float* __restrict__ out,
                                int N, int M) {
    extern __shared__ float sg[];   // M * 12 floats
    const int tid = threadIdx.x;
    const int b = blockIdx.x;

    for (int i = tid; i < M * 12; i += blockDim.x) sg[i] = g_gt[i];
    __syncthreads();

    // Pred box (computed redundantly by all threads; cheap, broadcast loads)
    const float* pb = box_pred + b * 7;
    float px_ = pb[0], py_ = pb[1], pdx = pb[3], pdy = pb[4], pyaw = pb[6];
    float pax[4], pay[4];
    box_corners(px_, py_, pdx, pdy, pyaw, pax, pay);
    const float area_a = pdx * pdy;
    const float ra = 0.5f * sqrtf(pdx * pdx + pdy * pdy);

    float best = 0.0f;

    for (int j = tid; j < M; j += blockDim.x) {
        const float* g = sg + j * 12;

        // Bounding-circle early out (kills ~99.6% of pairs)
        float ddx = g[9] - px_, ddy = g[10] - py_;
        float rr = ra + g[11];
        if (ddx * ddx + ddy * ddy > rr * rr) continue;

        // Sutherland–Hodgman: clip pred quad by gt quad's 4 half-planes.
        float ax[8], ay[8], qx[8], qy[8];
        #pragma unroll
        for (int k = 0; k < 4; k++) { ax[k] = pax[k]; ay[k] = pay[k]; }
        int n = 4;

        #pragma unroll
        for (int e = 0; e < 4; e++) {
            if (n == 0) break;
            float bpx = g[2 * e], bpy = g[2 * e + 1];
            int e2 = (e + 1) & 3;
            float ex = g[2 * e2] - bpx;
            float ey = g[2 * e2 + 1] - bpy;

            int m = 0;
            float sxv = ax[n - 1], syv = ay[n - 1];
            float ds = ex * (syv - bpy) - ey * (sxv - bpx);
            for (int i = 0; i < n; i++) {
                float txv = ax[i], tyv = ay[i];
                float dt = ex * (tyv - bpy) - ey * (txv - bpx);
                bool ins = (ds >= 0.0f);
                bool int_ = (dt >= 0.0f);
                if (ins) { qx[m] = sxv; qy[m] = syv; m++; }
                if (ins != int_) {
                    float t = ds / (ds - dt);
                    qx[m] = fmaf(t, txv - sxv, sxv);
                    qy[m] = fmaf(t, tyv - syv, syv);
                    m++;
                }
                sxv = txv; syv = tyv; ds = dt;
            }
            n = m;
            for (int i = 0; i < n; i++) { ax[i] = qx[i]; ay[i] = qy[i]; }
        }

        float inter = 0.0f;
        if (n >= 3) {
            float acc = 0.0f;
            float sxv = ax[n - 1], syv = ay[n - 1];
            for (int i = 0; i < n; i++) {
                acc += sxv * ay[i] - ax[i] * syv;
                sxv = ax[i]; syv = ay[i];
            }
            inter = 0.5f * fabsf(acc);
        }

        float uni = fmaxf(area_a + g[8] - inter, 1e-8f);
        best = fmaxf(best, inter / uni);
    }

    // Block max reduction
    __shared__ float wmax[32];
    #pragma unroll
    for (int o = 16; o > 0; o >>= 1)
        best = fmaxf(best, __shfl_xor_sync(0xffffffffu, best, o));
    int wid = tid >> 5, lane = tid & 31;
    if (lane == 0) wmax[wid] = best;
    __syncthreads();

    if (tid == 0) {
        int nw = blockDim.x >> 5;
        float mx = wmax[0];
        for (int w = 1; w < nw; w++) mx = fmaxf(mx, wmax[w]);

        // num_total_pos dtype disambiguation: int32 vs float32 bits
        int iv = *(const int*)ntp_raw;
        float fv = __int_as_float(iv);
        float ntp = (iv > 0 && iv < 100000000) ? (float)iv : fv;
        float denom = ntp + 1e-4f;

        float target = 2.0f * mx - 1.0f;
        float v = fabsf(iou_pred[b] - target);
        atomicAdd(out, v / denom);
    }
}

extern "C" void kernel_launch(void* const* d_in, const int* in_sizes, int n_in,
                              void* d_out, int out_size) {
    const float* iou_pred = (const float*)d_in[0];
    const float* box_pred = (const float*)d_in[1];
    const float* box_gt   = (const float*)d_in[2];
    const void*  ntp      = d_in[3];

    int N = in_sizes[1] / 7;
    int M = in_sizes[2] / 7;
    if (M > MAX_M) M = MAX_M;   // scratch bound (never hit for this problem)

    float* out = (float*)d_out;

    int pthreads = 128;
    int pblocks = (M + pthreads - 1) / pthreads;
    if (pblocks * pthreads < out_size)
        pblocks = (out_size + pthreads - 1) / pthreads;
    prep_kernel<<<pblocks, pthreads>>>(box_gt, M, out, out_size);

    size_t smem = (size_t)M * 12 * sizeof(float);
    if (smem > 48 * 1024) {
        cudaFuncSetAttribute(iou_loss_kernel,
                             cudaFuncAttributeMaxDynamicSharedMemorySize,
                             (int)smem);
    }
    iou_loss_kernel<<<N, 128, smem>>>(iou_pred, box_pred, ntp, out, N, M);
}

// round 2
// speedup vs baseline: 1.4724x; 1.4724x over previous
#include <cuda_runtime.h>
#include <math.h>

__device__ __forceinline__ void box_corners(float x, float y, float dx, float dy,
                                            float yaw, float* cx, float* cy) {
    float hx = 0.5f * dx, hy = 0.5f * dy;
    float s, c;
    sincosf(yaw, &s, &c);
    cx[0] = x + c * hx - s * hy;  cy[0] = y + s * hx + c * hy;
    cx[1] = x - c * hx - s * hy;  cy[1] = y - s * hx + c * hy;
    cx[2] = x - c * hx + s * hy;  cy[2] = y - s * hx - c * hy;
    cx[3] = x + c * hx + s * hy;  cy[3] = y + s * hx - c * hy;
}

// Tiny prep: zero the scalar output accumulator.
__global__ void zero_kernel(float* __restrict__ out, int out_size) {
    int j = blockIdx.x * blockDim.x + threadIdx.x;
    if (j < out_size) out[j] = 0.0f;
}

// One warp per pred box. GT table staged in shared once per block (8 preds).
// SoA: centers+radius for the hot early-out loop; corners+area for survivors.
__global__ void iou_loss_kernel(const float* __restrict__ iou_pred,
                                const float* __restrict__ box_pred,
                                const float* __restrict__ box_gt,
                                const void* __restrict__ ntp_raw,
                                float* __restrict__ out,
                                int N, int M) {
    extern __shared__ float sm[];
    float* scx  = sm;            // M  gt center x
    float* scy  = sm + M;        // M  gt center y
    float* srr  = sm + 2 * M;    // M  gt enclosing radius
    float* sdat = sm + 3 * M;    // M*9: 4 corners (x,y) + area
    __shared__ float blk_acc;

    const int tid = threadIdx.x;
    if (tid == 0) blk_acc = 0.0f;

    // Stage GT: compute corners directly from raw boxes.
    for (int j = tid; j < M; j += blockDim.x) {
        const float* b = box_gt + j * 7;
        float x = b[0], y = b[1], dx = b[3], dy = b[4], yaw = b[6];
        float cx[4], cy[4];
        box_corners(x, y, dx, dy, yaw, cx, cy);
        scx[j] = x; scy[j] = y;
        srr[j] = 0.5f * sqrtf(dx * dx + dy * dy);
        float* g = sdat + j * 9;
        #pragma unroll
        for (int k = 0; k < 4; k++) { g[2 * k] = cx[k]; g[2 * k + 1] = cy[k]; }
        g[8] = dx * dy;
    }
    __syncthreads();

    // num_total_pos dtype disambiguation: int32 vs float32 bits
    int iv = *(const int*)ntp_raw;
    float fv = __int_as_float(iv);
    float ntp = (iv > 0 && iv < 100000000) ? (float)iv : fv;
    const float inv_denom = 1.0f / (ntp + 1e-4f);

    const int lane    = tid & 31;
    const int warp_id = blockIdx.x * (blockDim.x >> 5) + (tid >> 5);
    const int nwarps  = gridDim.x * (blockDim.x >> 5);

    float local_sum = 0.0f;

    for (int i = warp_id; i < N; i += nwarps) {
        const float* pb = box_pred + i * 7;
        float px_ = pb[0], py_ = pb[1], pdx = pb[3], pdy = pb[4], pyaw = pb[6];
        float pax[4], pay[4];
        box_corners(px_, py_, pdx, pdy, pyaw, pax, pay);
        const float area_a = pdx * pdy;
        const float ra = 0.5f * sqrtf(pdx * pdx + pdy * pdy);

        float best = 0.0f;

        for (int j = lane; j < M; j += 32) {
            // Bounding-circle early out (kills ~99.6% of pairs)
            float ddx = scx[j] - px_, ddy = scy[j] - py_;
            float rr = ra + srr[j];
            if (ddx * ddx + ddy * ddy > rr * rr) continue;

            const float* g = sdat + j * 9;

            // Sutherland–Hodgman: clip pred quad by gt quad's 4 half-planes.
            float ax[8], ay[8], qx[8], qy[8];
            #pragma unroll
            for (int k = 0; k < 4; k++) { ax[k] = pax[k]; ay[k] = pay[k]; }
            int n = 4;

            #pragma unroll
            for (int e = 0; e < 4; e++) {
                if (n == 0) break;
                float bpx = g[2 * e], bpy = g[2 * e + 1];
                int e2 = (e + 1) & 3;
                float ex = g[2 * e2] - bpx;
                float ey = g[2 * e2 + 1] - bpy;

                int m = 0;
                float sxv = ax[n - 1], syv = ay[n - 1];
                float ds = ex * (syv - bpy) - ey * (sxv - bpx);
                for (int ii = 0; ii < n; ii++) {
                    float txv = ax[ii], tyv = ay[ii];
                    float dt = ex * (tyv - bpy) - ey * (txv - bpx);
                    bool ins  = (ds >= 0.0f);
                    bool int_ = (dt >= 0.0f);
                    if (ins) { qx[m] = sxv; qy[m] = syv; m++; }
                    if (ins != int_) {
                        float t = ds / (ds - dt);
                        qx[m] = fmaf(t, txv - sxv, sxv);
                        qy[m] = fmaf(t, tyv - syv, syv);
                        m++;
                    }
                    sxv = txv; syv = tyv; ds = dt;
                }
                n = m;
                for (int ii = 0; ii < n; ii++) { ax[ii] = qx[ii]; ay[ii] = qy[ii]; }
            }

            float inter = 0.0f;
            if (n >= 3) {
                float acc = 0.0f;
                float sxv = ax[n - 1], syv = ay[n - 1];
                for (int ii = 0; ii < n; ii++) {
                    acc += sxv * ay[ii] - ax[ii] * syv;
                    sxv = ax[ii]; syv = ay[ii];
                }
                inter = 0.5f * fabsf(acc);
            }

            float uni = fmaxf(area_a + g[8] - inter, 1e-8f);
            best = fmaxf(best, inter / uni);
        }

        // Warp max reduction
        #pragma unroll
        for (int o = 16; o > 0; o >>= 1)
            best = fmaxf(best, __shfl_xor_sync(0xffffffffu, best, o));

        if (lane == 0) {
            float target = 2.0f * best - 1.0f;
            local_sum += fabsf(iou_pred[i] - target);
        }
    }

    if (lane == 0 && local_sum != 0.0f)
        atomicAdd(&blk_acc, local_sum * inv_denom);
    __syncthreads();
    if (tid == 0 && blk_acc != 0.0f)
        atomicAdd(out, blk_acc);
}

extern "C" void kernel_launch(void* const* d_in, const int* in_sizes, int n_in,
                              void* d_out, int out_size) {
    const float* iou_pred = (const float*)d_in[0];
    const float* box_pred = (const float*)d_in[1];
    const float* box_gt   = (const float*)d_in[2];
    const void*  ntp      = d_in[3];

    int N = in_sizes[1] / 7;
    int M = in_sizes[2] / 7;

    float* out = (float*)d_out;

    zero_kernel<<<(out_size + 255) / 256, 256>>>(out, out_size);

    const int threads = 256;
    const int warps_per_block = threads / 32;
    int grid = (N + warps_per_block - 1) / warps_per_block;   // one warp per pred

    size_t smem = (size_t)M * 12 * sizeof(float);
    if (smem > 48 * 1024) {
        cudaFuncSetAttribute(iou_loss_kernel,
                             cudaFuncAttributeMaxDynamicSharedMemorySize,
                             (int)smem);
    }
    iou_loss_kernel<<<grid, threads, smem>>>(iou_pred, box_pred, box_gt, ntp,
                                             out, N, M);
}

// round 3
// speedup vs baseline: 3.8162x; 2.5919x over previous
#include <cuda_runtime.h>
#include <math.h>

#define TPB   512
#define NWARP (TPB / 32)

__global__ void zero_kernel(float* __restrict__ out, int n) {
    int i = blockIdx.x * blockDim.x + threadIdx.x;
    if (i < n) out[i] = 0.0f;
}

// Branchless Liang-Barsky segment clip vs axis-aligned box [-hx,hx]x[-hy,hy].
// (px,py)+t(dx,dy) in the box's local frame gives t-interval; endpoints are
// evaluated in the common (o_B-relative world) frame for the shoelace term.
// Returns start x end contribution (0 if the clipped segment is empty).
__device__ __forceinline__ float seg_contrib(
    float px, float py, float dx, float dy, float hx, float hy,
    float pwx, float pwy, float dwx, float dwy)
{
    float t0 = 0.0f, t1 = 1.0f;
    float ix = 1.0f / dx;                 // +-inf when dx==0: handled by min/max
    float ta = (-hx - px) * ix, tb = (hx - px) * ix;
    t0 = fmaxf(t0, fminf(ta, tb));
    t1 = fminf(t1, fmaxf(ta, tb));
    float iy = 1.0f / dy;
    float tc = (-hy - py) * iy, td = (hy - py) * iy;
    t0 = fmaxf(t0, fminf(tc, td));
    t1 = fminf(t1, fmaxf(tc, td));

    float sx = fmaf(t0, dwx, pwx), sy = fmaf(t0, dwy, pwy);
    float ex = fmaf(t1, dwx, pwx), ey = fmaf(t1, dwy, pwy);
    float cr = sx * ey - sy * ex;
    return (t1 >= t0) ? cr : 0.0f;
}

__global__ void __launch_bounds__(TPB)
iou_loss_kernel(const float* __restrict__ iou_pred,
                const float* __restrict__ box_pred,
                const float* __restrict__ box_gt,
                const void* __restrict__ ntp_raw,
                float* __restrict__ out,
                int N, int M)
{
    extern __shared__ unsigned char smraw[];
    float4* sA = (float4*)smraw;            // (cx, cy, radius, area)
    float4* sB = sA + M;                    // (cos, sin, hx, hy)
    unsigned short* qbase = (unsigned short*)(sB + M);  // per-warp queues [NWARP][M]
    __shared__ float blk_acc;

    const int tid = threadIdx.x;
    if (tid == 0) blk_acc = 0.0f;

    // Stage GT as SoA float4 pairs, computed from raw boxes.
    for (int j = tid; j < M; j += TPB) {
        const float* b = box_gt + j * 7;
        float x = b[0], y = b[1], dx = b[3], dy = b[4], yaw = b[6];
        float s, c;
        sincosf(yaw, &s, &c);
        sA[j] = make_float4(x, y, 0.5f * sqrtf(dx * dx + dy * dy), dx * dy);
        sB[j] = make_float4(c, s, 0.5f * dx, 0.5f * dy);
    }
    __syncthreads();

    // num_total_pos dtype disambiguation: int32 vs float32 bits
    int iv = *(const int*)ntp_raw;
    float fv = __int_as_float(iv);
    float ntp = (iv > 0 && iv < 100000000) ? (float)iv : fv;
    const float inv_denom = 1.0f / (ntp + 1e-4f);

    const int lane    = tid & 31;
    const int wslot   = tid >> 5;
    const int warp_id = blockIdx.x * NWARP + wslot;
    const int nwarps  = gridDim.x * NWARP;
    unsigned short* q = qbase + wslot * M;

    float local_sum = 0.0f;

    for (int i = warp_id; i < N; i += nwarps) {
        const float* pb = box_pred + i * 7;
        float px_ = pb[0], py_ = pb[1];
        float hax = 0.5f * pb[3], hay = 0.5f * pb[4];
        float sa, ca;
        sincosf(pb[6], &sa, &ca);
        const float area_a = 4.0f * hax * hay;
        const float ra = sqrtf(hax * hax + hay * hay);

        // A corners (world, CCW)
        float wx[4], wy[4];
        {
            const float lx[4] = {hax, -hax, -hax, hax};
            const float ly[4] = {hay, hay, -hay, -hay};
            #pragma unroll
            for (int k = 0; k < 4; k++) {
                wx[k] = px_ + ca * lx[k] - sa * ly[k];
                wy[k] = py_ + sa * lx[k] + ca * ly[k];
            }
        }

        // ---- Phase 1: circle-test scan with warp compaction into queue ----
        int cnt = 0;
        for (int t = 0; t < (M + 31) / 32; t++) {
            int j = t * 32 + lane;
            bool ok = false;
            if (j < M) {
                float4 A4 = sA[j];
                float ddx = A4.x - px_, ddy = A4.y - py_;
                float rr = ra + A4.z;
                ok = (ddx * ddx + ddy * ddy <= rr * rr);
            }
            unsigned m = __ballot_sync(0xffffffffu, ok);
            if (ok) q[cnt + __popc(m & ((1u << lane) - 1u))] = (unsigned short)j;
            cnt += __popc(m);
        }

        // ---- Phase 2: dense branchless clip over survivors ----
        float best = 0.0f;
        for (int k = lane; k < cnt; k += 32) {
            int j = q[k];
            float4 A4 = sA[j];
            float4 B4 = sB[j];
            float bx = A4.x, by = A4.y, area_b = A4.w;
            float cb = B4.x, sb = B4.y, hbx = B4.z, hby = B4.w;

            // A corners relative to o_B (common frame) and in B-local frame
            float rax[4], ray[4], lax[4], lay[4];
            #pragma unroll
            for (int kk = 0; kk < 4; kk++) {
                rax[kk] = wx[kk] - bx;
                ray[kk] = wy[kk] - by;
                lax[kk] =  cb * rax[kk] + sb * ray[kk];
                lay[kk] = -sb * rax[kk] + cb * ray[kk];
            }

            float total = 0.0f;
            #pragma unroll
            for (int kk = 0; kk < 4; kk++) {
                int kn = (kk + 1) & 3;
                total += seg_contrib(lax[kk], lay[kk],
                                     lax[kn] - lax[kk], lay[kn] - lay[kk],
                                     hbx, hby,
                                     rax[kk], ray[kk],
                                     rax[kn] - rax[kk], ray[kn] - ray[kk]);
            }

            // B corners: rel-world (rel to o_B) and in A-local frame
            const float lbx[4] = {hbx, -hbx, -hbx, hbx};
            const float lby[4] = {hby, hby, -hby, -hby};
            float rbx[4], rby[4], qx[4], qy[4];
            float ox = bx - px_, oy = by - py_;
            #pragma unroll
            for (int kk = 0; kk < 4; kk++) {
                rbx[kk] = cb * lbx[kk] - sb * lby[kk];
                rby[kk] = sb * lbx[kk] + cb * lby[kk];
                float tx = rbx[kk] + ox, ty = rby[kk] + oy;
                qx[kk] =  ca * tx + sa * ty;
                qy[kk] = -sa * tx + ca * ty;
            }
            #pragma unroll
            for (int kk = 0; kk < 4; kk++) {
                int kn = (kk + 1) & 3;
                total += seg_contrib(qx[kk], qy[kk],
                                     qx[kn] - qx[kk], qy[kn] - qy[kk],
                                     hax, hay,
                                     rbx[kk], rby[kk],
                                     rbx[kn] - rbx[kk], rby[kn] - rby[kk]);
            }

            float inter = 0.5f * fabsf(total);
            float uni = fmaxf(area_a + area_b - inter, 1e-8f);
            best = fmaxf(best, inter / uni);
        }

        // Warp max reduction
        #pragma unroll
        for (int o = 16; o > 0; o >>= 1)
            best = fmaxf(best, __shfl_xor_sync(0xffffffffu, best, o));

        if (lane == 0) {
            float target = 2.0f * best - 1.0f;
            local_sum += fabsf(iou_pred[i] - target);
        }
    }

    if (lane == 0)
        atomicAdd(&blk_acc, local_sum * inv_denom);
    __syncthreads();
    if (tid == 0)
        atomicAdd(out, blk_acc);
}

extern "C" void kernel_launch(void* const* d_in, const int* in_sizes, int n_in,
                              void* d_out, int out_size) {
    const float* iou_pred = (const float*)d_in[0];
    const float* box_pred = (const float*)d_in[1];
    const float* box_gt   = (const float*)d_in[2];
    const void*  ntp      = d_in[3];

    int N = in_sizes[1] / 7;
    int M = in_sizes[2] / 7;

    float* out = (float*)d_out;

    zero_kernel<<<(out_size + 255) / 256, 256>>>(out, out_size);

    int grid = (N + NWARP - 1) / NWARP;   // one warp per pred, single wave
    size_t smem = (size_t)M * sizeof(float4) * 2
                + (size_t)NWARP * M * sizeof(unsigned short);
    if (smem > 48 * 1024) {
        cudaFuncSetAttribute(iou_loss_kernel,
                             cudaFuncAttributeMaxDynamicSharedMemorySize,
                             (int)smem);
    }
    iou_loss_kernel<<<grid, TPB, smem>>>(iou_pred, box_pred, box_gt, ntp,
                                         out, N, M);
}